// round 15
// baseline (speedup 1.0000x reference)
#include <cuda_runtime.h>
#include <cuda_fp16.h>
#include <math.h>

#define N_NODES 50000
#define N_EDGES 1600000
// IN_DIM = 128, HEADS*HIDDEN = 128, OUT_DIM = 64

// ---------------- static device scratch ----------------
__device__ int    g_deg[N_NODES];
__device__ int    g_rs[N_NODES + 1];
__device__ int    g_rank[N_EDGES];
__device__ int    g_col[N_EDGES];
__device__ __half g_feat1h[N_NODES * 128];
__device__ float  g_h1[N_NODES * 128];
__device__ __half g_feat2h[N_NODES * 64];

// ---------------- CSR build (rank trick), 4 edges/thread ----------------
__global__ void k_hist(const int* __restrict__ dst) {
    int i = blockIdx.x * blockDim.x + threadIdx.x;
    int base = i * 4;
    if (base + 3 < N_EDGES) {
        int4 d = *reinterpret_cast<const int4*>(dst + base);
        int4 r;
        r.x = atomicAdd(&g_deg[d.x], 1);
        r.y = atomicAdd(&g_deg[d.y], 1);
        r.z = atomicAdd(&g_deg[d.z], 1);
        r.w = atomicAdd(&g_deg[d.w], 1);
        *reinterpret_cast<int4*>(g_rank + base) = r;
    } else {
        for (int j = base; j < N_EDGES; j++)
            g_rank[j] = atomicAdd(&g_deg[dst[j]], 1);
    }
}

__global__ void k_scan() {
    __shared__ int sums[1024];
    const int PER = (N_NODES + 1023) / 1024;  // 49
    int t = threadIdx.x;
    int beg = t * PER;
    int end = min(beg + PER, N_NODES);
    int s = 0;
    for (int i = beg; i < end; i++) s += g_deg[i];
    sums[t] = s;
    __syncthreads();
    for (int off = 1; off < 1024; off <<= 1) {
        int v = (t >= off) ? sums[t - off] : 0;
        __syncthreads();
        sums[t] += v;
        __syncthreads();
    }
    int run = (t == 0) ? 0 : sums[t - 1];
    for (int i = beg; i < end; i++) {
        g_rs[i] = run;
        run += g_deg[i];
    }
    if (t == 1023) g_rs[N_NODES] = run;
}

// atomic-free scatter fill, 4 edges/thread
__global__ void k_fill(const int* __restrict__ src, const int* __restrict__ dst) {
    int i = blockIdx.x * blockDim.x + threadIdx.x;
    int base = i * 4;
    if (base + 3 < N_EDGES) {
        int4 d = *reinterpret_cast<const int4*>(dst + base);
        int4 r = *reinterpret_cast<const int4*>(g_rank + base);
        int4 s = *reinterpret_cast<const int4*>(src + base);
        g_col[g_rs[d.x] + r.x] = s.x;
        g_col[g_rs[d.y] + r.y] = s.y;
        g_col[g_rs[d.z] + r.z] = s.z;
        g_col[g_rs[d.w] + r.w] = s.w;
    } else {
        for (int j = base; j < N_EDGES; j++)
            g_col[g_rs[dst[j]] + g_rank[j]] = src[j];
    }
}

// ---------------- tf32 tensor-core GEMM -> fp16 table ----------------
__device__ __forceinline__ unsigned cvt_tf32(float x) {
    unsigned r;
    asm("cvt.rna.tf32.f32 %0, %1;" : "=r"(r) : "f"(x));
    return r;
}

__device__ __forceinline__ void mma_tf32(float c[4], unsigned a0, unsigned a1,
                                         unsigned a2, unsigned a3,
                                         unsigned b0, unsigned b1) {
    asm("mma.sync.aligned.m16n8k8.row.col.f32.tf32.tf32.f32 "
        "{%0,%1,%2,%3}, {%4,%5,%6,%7}, {%8,%9}, {%0,%1,%2,%3};"
        : "+f"(c[0]), "+f"(c[1]), "+f"(c[2]), "+f"(c[3])
        : "r"(a0), "r"(a1), "r"(a2), "r"(a3), "r"(b0), "r"(b1));
}

template <int MOUT>
__global__ __launch_bounds__(256) void k_gemm_tc(const float* __restrict__ X,
                                                 const float* __restrict__ W,
                                                 __half* __restrict__ Yh) {
    constexpr int NT = MOUT / 8;
    constexpr int WS = MOUT + 8;
    __shared__ unsigned Xs[128 * 36];
    __shared__ unsigned Ws[32 * WS];

    const int tid = threadIdx.x;
    const int lane = tid & 31;
    const int wid = tid >> 5;
    const int g = lane >> 2;
    const int tc = lane & 3;
    const int row0 = blockIdx.x * 128;

    float acc[NT][4];
#pragma unroll
    for (int nt = 0; nt < NT; nt++)
#pragma unroll
        for (int j = 0; j < 4; j++) acc[nt][j] = 0.f;

#pragma unroll
    for (int kt = 0; kt < 4; kt++) {
#pragma unroll
        for (int it = 0; it < 4; it++) {
            int idx = tid + it * 256;
            int r = idx >> 3, kq = idx & 7;
            float4 v = make_float4(0.f, 0.f, 0.f, 0.f);
            int gr = row0 + r;
            if (gr < N_NODES)
                v = *reinterpret_cast<const float4*>(X + gr * 128 + kt * 32 + kq * 4);
            uint4 u = make_uint4(cvt_tf32(v.x), cvt_tf32(v.y), cvt_tf32(v.z), cvt_tf32(v.w));
            *reinterpret_cast<uint4*>(&Xs[r * 36 + kq * 4]) = u;
        }
        for (int idx = tid; idx < 32 * MOUT / 4; idx += 256) {
            int k = idx / (MOUT / 4), c4 = idx % (MOUT / 4);
            float4 wv = *reinterpret_cast<const float4*>(W + (kt * 32 + k) * MOUT + c4 * 4);
            uint4 u = make_uint4(cvt_tf32(wv.x), cvt_tf32(wv.y), cvt_tf32(wv.z), cvt_tf32(wv.w));
            *reinterpret_cast<uint4*>(&Ws[k * WS + c4 * 4]) = u;
        }
        __syncthreads();

#pragma unroll
        for (int k8 = 0; k8 < 4; k8++) {
            unsigned a0 = Xs[(wid * 16 + g) * 36 + k8 * 8 + tc];
            unsigned a1 = Xs[(wid * 16 + g + 8) * 36 + k8 * 8 + tc];
            unsigned a2 = Xs[(wid * 16 + g) * 36 + k8 * 8 + tc + 4];
            unsigned a3 = Xs[(wid * 16 + g + 8) * 36 + k8 * 8 + tc + 4];
#pragma unroll
            for (int nt = 0; nt < NT; nt++) {
                unsigned b0 = Ws[(k8 * 8 + tc) * WS + nt * 8 + g];
                unsigned b1 = Ws[(k8 * 8 + tc + 4) * WS + nt * 8 + g];
                mma_tf32(acc[nt], a0, a1, a2, a3, b0, b1);
            }
        }
        __syncthreads();
    }

    int r0 = row0 + wid * 16 + g;
    int r1 = r0 + 8;
#pragma unroll
    for (int nt = 0; nt < NT; nt++) {
        int c = nt * 8 + tc * 2;
        if (r0 < N_NODES)
            *reinterpret_cast<__half2*>(Yh + r0 * MOUT + c) =
                __float22half2_rn(make_float2(acc[nt][0], acc[nt][1]));
        if (r1 < N_NODES)
            *reinterpret_cast<__half2*>(Yh + r1 * MOUT + c) =
                __float22half2_rn(make_float2(acc[nt][2], acc[nt][3]));
    }
}

// ---------------- GAT helpers ----------------
__device__ __forceinline__ float eluf(float x) {
    return x > 0.f ? x : expm1f(x);
}

__device__ __forceinline__ void cvt8(uint4 u, float2& a, float2& b, float2& c, float2& d) {
    a = __half22float2(*reinterpret_cast<__half2*>(&u.x));
    b = __half22float2(*reinterpret_cast<__half2*>(&u.y));
    c = __half22float2(*reinterpret_cast<__half2*>(&u.z));
    d = __half22float2(*reinterpret_cast<__half2*>(&u.w));
}

// ---------------- fused GAT layer 1: half-warp/node, 8 fp16 dims/lane ----------------
__global__ __launch_bounds__(256) void k_gat1() {
    int t = blockIdx.x * blockDim.x + threadIdx.x;
    int w = t >> 4;
    if (w >= N_NODES) return;
    int lane = threadIdx.x & 15;
    unsigned mask = 0xFFFFu << (threadIdx.x & 16);

    const __half* fp = g_feat1h;
    uint4 ud = *reinterpret_cast<const uint4*>(fp + w * 128 + lane * 8);
    float2 d0, d1, d2, d3;
    cvt8(ud, d0, d1, d2, d3);

    float c0 = 0.f, c1 = 0.f, c2 = 0.f, c3 = 0.f;
    float c4 = 0.f, c5 = 0.f, c6 = 0.f, c7 = 0.f;
    float den = 0.f;

    int i = g_rs[w], end = g_rs[w + 1];
    for (; i + 1 < end; i += 2) {
        int s0 = g_col[i], s1 = g_col[i + 1];
        uint4 u0 = *reinterpret_cast<const uint4*>(fp + s0 * 128 + lane * 8);
        uint4 u1 = *reinterpret_cast<const uint4*>(fp + s1 * 128 + lane * 8);
        float2 a0, a1, a2, a3, b0, b1, b2, b3;
        cvt8(u0, a0, a1, a2, a3);
        cvt8(u1, b0, b1, b2, b3);
        float p0 = a0.x * d0.x + a0.y * d0.y + a1.x * d1.x + a1.y * d1.y
                 + a2.x * d2.x + a2.y * d2.y + a3.x * d3.x + a3.y * d3.y;
        float p1 = b0.x * d0.x + b0.y * d0.y + b1.x * d1.x + b1.y * d1.y
                 + b2.x * d2.x + b2.y * d2.y + b3.x * d3.x + b3.y * d3.y;
        p0 += __shfl_xor_sync(mask, p0, 1);
        p1 += __shfl_xor_sync(mask, p1, 1);
        float q0 = __expf(p0 * 0.25f);    // HIDDEN^-0.5
        float q1 = __expf(p1 * 0.25f);
        den += q0 + q1;
        c0 += q0 * a0.x + q1 * b0.x;
        c1 += q0 * a0.y + q1 * b0.y;
        c2 += q0 * a1.x + q1 * b1.x;
        c3 += q0 * a1.y + q1 * b1.y;
        c4 += q0 * a2.x + q1 * b2.x;
        c5 += q0 * a2.y + q1 * b2.y;
        c6 += q0 * a3.x + q1 * b3.x;
        c7 += q0 * a3.y + q1 * b3.y;
    }
    if (i < end) {
        int s0 = g_col[i];
        uint4 u0 = *reinterpret_cast<const uint4*>(fp + s0 * 128 + lane * 8);
        float2 a0, a1, a2, a3;
        cvt8(u0, a0, a1, a2, a3);
        float p0 = a0.x * d0.x + a0.y * d0.y + a1.x * d1.x + a1.y * d1.y
                 + a2.x * d2.x + a2.y * d2.y + a3.x * d3.x + a3.y * d3.y;
        p0 += __shfl_xor_sync(mask, p0, 1);
        float q0 = __expf(p0 * 0.25f);
        den += q0;
        c0 += q0 * a0.x; c1 += q0 * a0.y; c2 += q0 * a1.x; c3 += q0 * a1.y;
        c4 += q0 * a2.x; c5 += q0 * a2.y; c6 += q0 * a3.x; c7 += q0 * a3.y;
    }

    float inv = 1.f / fmaxf(den, 1e-9f);
    float* op = g_h1 + w * 128 + lane * 8;
    *reinterpret_cast<float4*>(op) =
        make_float4(eluf(c0 * inv), eluf(c1 * inv), eluf(c2 * inv), eluf(c3 * inv));
    *reinterpret_cast<float4*>(op + 4) =
        make_float4(eluf(c4 * inv), eluf(c5 * inv), eluf(c6 * inv), eluf(c7 * inv));
}

// ---------------- fused GAT layer 2: 8 lanes/node, 8 fp16 dims/lane ----------------
__global__ __launch_bounds__(256) void k_gat2(float* __restrict__ out) {
    int t = blockIdx.x * blockDim.x + threadIdx.x;
    int w = t >> 3;
    if (w >= N_NODES) return;
    int lane = threadIdx.x & 7;
    unsigned mask = 0xFFu << (threadIdx.x & 24);

    const __half* fp = g_feat2h;
    uint4 ud = *reinterpret_cast<const uint4*>(fp + w * 64 + lane * 8);
    float2 d0, d1, d2, d3;
    cvt8(ud, d0, d1, d2, d3);

    float c0 = 0.f, c1 = 0.f, c2 = 0.f, c3 = 0.f;
    float c4 = 0.f, c5 = 0.f, c6 = 0.f, c7 = 0.f;
    float den = 0.f;

    int i = g_rs[w], end = g_rs[w + 1];
    for (; i + 1 < end; i += 2) {
        int s0 = g_col[i], s1 = g_col[i + 1];
        uint4 u0 = *reinterpret_cast<const uint4*>(fp + s0 * 64 + lane * 8);
        uint4 u1 = *reinterpret_cast<const uint4*>(fp + s1 * 64 + lane * 8);
        float2 a0, a1, a2, a3, b0, b1, b2, b3;
        cvt8(u0, a0, a1, a2, a3);
        cvt8(u1, b0, b1, b2, b3);
        float p0 = a0.x * d0.x + a0.y * d0.y + a1.x * d1.x + a1.y * d1.y
                 + a2.x * d2.x + a2.y * d2.y + a3.x * d3.x + a3.y * d3.y;
        float p1 = b0.x * d0.x + b0.y * d0.y + b1.x * d1.x + b1.y * d1.y
                 + b2.x * d2.x + b2.y * d2.y + b3.x * d3.x + b3.y * d3.y;
#pragma unroll
        for (int off = 4; off; off >>= 1) {
            p0 += __shfl_xor_sync(mask, p0, off);
            p1 += __shfl_xor_sync(mask, p1, off);
        }
        float q0 = __expf(p0 * 0.125f);   // 64^-0.5
        float q1 = __expf(p1 * 0.125f);
        den += q0 + q1;
        c0 += q0 * a0.x + q1 * b0.x;
        c1 += q0 * a0.y + q1 * b0.y;
        c2 += q0 * a1.x + q1 * b1.x;
        c3 += q0 * a1.y + q1 * b1.y;
        c4 += q0 * a2.x + q1 * b2.x;
        c5 += q0 * a2.y + q1 * b2.y;
        c6 += q0 * a3.x + q1 * b3.x;
        c7 += q0 * a3.y + q1 * b3.y;
    }
    if (i < end) {
        int s0 = g_col[i];
        uint4 u0 = *reinterpret_cast<const uint4*>(fp + s0 * 64 + lane * 8);
        float2 a0, a1, a2, a3;
        cvt8(u0, a0, a1, a2, a3);
        float p0 = a0.x * d0.x + a0.y * d0.y + a1.x * d1.x + a1.y * d1.y
                 + a2.x * d2.x + a2.y * d2.y + a3.x * d3.x + a3.y * d3.y;
#pragma unroll
        for (int off = 4; off; off >>= 1)
            p0 += __shfl_xor_sync(mask, p0, off);
        float q0 = __expf(p0 * 0.125f);
        den += q0;
        c0 += q0 * a0.x; c1 += q0 * a0.y; c2 += q0 * a1.x; c3 += q0 * a1.y;
        c4 += q0 * a2.x; c5 += q0 * a2.y; c6 += q0 * a3.x; c7 += q0 * a3.y;
    }

    float inv = 1.f / fmaxf(den, 1e-9f);
    float* op = out + w * 64 + lane * 8;
    *reinterpret_cast<float4*>(op) = make_float4(c0 * inv, c1 * inv, c2 * inv, c3 * inv);
    *reinterpret_cast<float4*>(op + 4) = make_float4(c4 * inv, c5 * inv, c6 * inv, c7 * inv);
}

// ---------------- launch: gemm1 on HIGH-PRIORITY side stream || CSR chain ----------------
extern "C" void kernel_launch(void* const* d_in, const int* in_sizes, int n_in,
                              void* d_out, int out_size) {
    const float* h   = (const float*)d_in[0];
    const float* W1  = (const float*)d_in[1];
    const float* W2  = (const float*)d_in[2];
    const int*   src = (const int*)d_in[3];
    const int*   dst = (const int*)d_in[4];
    float*       out = (float*)d_out;

    __half *p_f1h = nullptr, *p_f2h = nullptr;
    float  *p_h1 = nullptr;
    int    *p_deg = nullptr;
    cudaGetSymbolAddress((void**)&p_f1h, g_feat1h);
    cudaGetSymbolAddress((void**)&p_h1, g_h1);
    cudaGetSymbolAddress((void**)&p_f2h, g_feat2h);
    cudaGetSymbolAddress((void**)&p_deg, g_deg);

    // one-time high-priority side stream + events (first, uncaptured call only)
    static cudaStream_t s_side = nullptr;
    static cudaEvent_t ev_fork = nullptr, ev_join = nullptr;
    if (s_side == nullptr) {
        int lo = 0, hi = 0;
        cudaDeviceGetStreamPriorityRange(&lo, &hi);  // hi = greatest priority
        cudaStreamCreateWithPriority(&s_side, cudaStreamNonBlocking, hi);
        cudaEventCreateWithFlags(&ev_fork, cudaEventDisableTiming);
        cudaEventCreateWithFlags(&ev_join, cudaEventDisableTiming);
    }

    const int TB = 256;
    const int GB = (N_NODES + 127) / 128;  // 391
    const int EB = (N_EDGES / 4 + TB - 1) / TB;

    // fork FIRST: gemm1 enters the device ahead of the CSR flood, at high priority
    cudaEventRecord(ev_fork, 0);
    cudaStreamWaitEvent(s_side, ev_fork, 0);
    k_gemm_tc<128><<<GB, 256, 0, s_side>>>(h, W1, p_f1h);
    cudaEventRecord(ev_join, s_side);

    // main stream: CSR build
    cudaMemsetAsync(p_deg, 0, N_NODES * sizeof(int));
    k_hist<<<EB, TB>>>(dst);
    k_scan<<<1, 1024>>>();
    k_fill<<<EB, TB>>>(src, dst);

    // join, then the dependent chain
    cudaStreamWaitEvent(0, ev_join, 0);
    k_gat1<<<(N_NODES * 16 + TB - 1) / TB, TB>>>();
    k_gemm_tc<64><<<GB, 256>>>(p_h1, W2, p_f2h);
    k_gat2<<<(N_NODES * 8 + TB - 1) / TB, TB>>>(out);
}

// round 16
// speedup vs baseline: 1.0238x; 1.0238x over previous
#include <cuda_runtime.h>
#include <cuda_fp16.h>
#include <math.h>

#define N_NODES 50000
#define N_EDGES 1600000
// IN_DIM = 128, HEADS*HIDDEN = 128, OUT_DIM = 64

// ---------------- static device scratch ----------------
__device__ int    g_deg[N_NODES];
__device__ int    g_rs[N_NODES + 1];
__device__ int    g_rank[N_EDGES];
__device__ int    g_col[N_EDGES];
__device__ __half g_feat1h[N_NODES * 128];
__device__ float  g_h1[N_NODES * 128];
__device__ __half g_feat2h[N_NODES * 64];

// ---------------- CSR build (rank trick), 4 edges/thread ----------------
__global__ void k_hist(const int* __restrict__ dst) {
    int i = blockIdx.x * blockDim.x + threadIdx.x;
    int base = i * 4;
    if (base + 3 < N_EDGES) {
        int4 d = *reinterpret_cast<const int4*>(dst + base);
        int4 r;
        r.x = atomicAdd(&g_deg[d.x], 1);
        r.y = atomicAdd(&g_deg[d.y], 1);
        r.z = atomicAdd(&g_deg[d.z], 1);
        r.w = atomicAdd(&g_deg[d.w], 1);
        *reinterpret_cast<int4*>(g_rank + base) = r;
    } else {
        for (int j = base; j < N_EDGES; j++)
            g_rank[j] = atomicAdd(&g_deg[dst[j]], 1);
    }
}

__global__ void k_scan() {
    __shared__ int sums[1024];
    const int PER = (N_NODES + 1023) / 1024;  // 49
    int t = threadIdx.x;
    int beg = t * PER;
    int end = min(beg + PER, N_NODES);
    int s = 0;
    for (int i = beg; i < end; i++) s += g_deg[i];
    sums[t] = s;
    __syncthreads();
    for (int off = 1; off < 1024; off <<= 1) {
        int v = (t >= off) ? sums[t - off] : 0;
        __syncthreads();
        sums[t] += v;
        __syncthreads();
    }
    int run = (t == 0) ? 0 : sums[t - 1];
    for (int i = beg; i < end; i++) {
        g_rs[i] = run;
        run += g_deg[i];
    }
    if (t == 1023) g_rs[N_NODES] = run;
}

// atomic-free scatter fill, 4 edges/thread
__global__ void k_fill(const int* __restrict__ src, const int* __restrict__ dst) {
    int i = blockIdx.x * blockDim.x + threadIdx.x;
    int base = i * 4;
    if (base + 3 < N_EDGES) {
        int4 d = *reinterpret_cast<const int4*>(dst + base);
        int4 r = *reinterpret_cast<const int4*>(g_rank + base);
        int4 s = *reinterpret_cast<const int4*>(src + base);
        g_col[g_rs[d.x] + r.x] = s.x;
        g_col[g_rs[d.y] + r.y] = s.y;
        g_col[g_rs[d.z] + r.z] = s.z;
        g_col[g_rs[d.w] + r.w] = s.w;
    } else {
        for (int j = base; j < N_EDGES; j++)
            g_col[g_rs[dst[j]] + g_rank[j]] = src[j];
    }
}

// ---------------- tf32 tensor-core GEMM -> fp16 table ----------------
__device__ __forceinline__ unsigned cvt_tf32(float x) {
    unsigned r;
    asm("cvt.rna.tf32.f32 %0, %1;" : "=r"(r) : "f"(x));
    return r;
}

__device__ __forceinline__ void mma_tf32(float c[4], unsigned a0, unsigned a1,
                                         unsigned a2, unsigned a3,
                                         unsigned b0, unsigned b1) {
    asm("mma.sync.aligned.m16n8k8.row.col.f32.tf32.tf32.f32 "
        "{%0,%1,%2,%3}, {%4,%5,%6,%7}, {%8,%9}, {%0,%1,%2,%3};"
        : "+f"(c[0]), "+f"(c[1]), "+f"(c[2]), "+f"(c[3])
        : "r"(a0), "r"(a1), "r"(a2), "r"(a3), "r"(b0), "r"(b1));
}

template <int MOUT>
__global__ __launch_bounds__(256) void k_gemm_tc(const float* __restrict__ X,
                                                 const float* __restrict__ W,
                                                 __half* __restrict__ Yh) {
    constexpr int NT = MOUT / 8;
    constexpr int WS = MOUT + 8;
    __shared__ unsigned Xs[128 * 36];
    __shared__ unsigned Ws[32 * WS];

    const int tid = threadIdx.x;
    const int lane = tid & 31;
    const int wid = tid >> 5;
    const int g = lane >> 2;
    const int tc = lane & 3;
    const int row0 = blockIdx.x * 128;

    float acc[NT][4];
#pragma unroll
    for (int nt = 0; nt < NT; nt++)
#pragma unroll
        for (int j = 0; j < 4; j++) acc[nt][j] = 0.f;

#pragma unroll
    for (int kt = 0; kt < 4; kt++) {
#pragma unroll
        for (int it = 0; it < 4; it++) {
            int idx = tid + it * 256;
            int r = idx >> 3, kq = idx & 7;
            float4 v = make_float4(0.f, 0.f, 0.f, 0.f);
            int gr = row0 + r;
            if (gr < N_NODES)
                v = *reinterpret_cast<const float4*>(X + gr * 128 + kt * 32 + kq * 4);
            uint4 u = make_uint4(cvt_tf32(v.x), cvt_tf32(v.y), cvt_tf32(v.z), cvt_tf32(v.w));
            *reinterpret_cast<uint4*>(&Xs[r * 36 + kq * 4]) = u;
        }
        for (int idx = tid; idx < 32 * MOUT / 4; idx += 256) {
            int k = idx / (MOUT / 4), c4 = idx % (MOUT / 4);
            float4 wv = *reinterpret_cast<const float4*>(W + (kt * 32 + k) * MOUT + c4 * 4);
            uint4 u = make_uint4(cvt_tf32(wv.x), cvt_tf32(wv.y), cvt_tf32(wv.z), cvt_tf32(wv.w));
            *reinterpret_cast<uint4*>(&Ws[k * WS + c4 * 4]) = u;
        }
        __syncthreads();

#pragma unroll
        for (int k8 = 0; k8 < 4; k8++) {
            unsigned a0 = Xs[(wid * 16 + g) * 36 + k8 * 8 + tc];
            unsigned a1 = Xs[(wid * 16 + g + 8) * 36 + k8 * 8 + tc];
            unsigned a2 = Xs[(wid * 16 + g) * 36 + k8 * 8 + tc + 4];
            unsigned a3 = Xs[(wid * 16 + g + 8) * 36 + k8 * 8 + tc + 4];
#pragma unroll
            for (int nt = 0; nt < NT; nt++) {
                unsigned b0 = Ws[(k8 * 8 + tc) * WS + nt * 8 + g];
                unsigned b1 = Ws[(k8 * 8 + tc + 4) * WS + nt * 8 + g];
                mma_tf32(acc[nt], a0, a1, a2, a3, b0, b1);
            }
        }
        __syncthreads();
    }

    int r0 = row0 + wid * 16 + g;
    int r1 = r0 + 8;
#pragma unroll
    for (int nt = 0; nt < NT; nt++) {
        int c = nt * 8 + tc * 2;
        if (r0 < N_NODES)
            *reinterpret_cast<__half2*>(Yh + r0 * MOUT + c) =
                __float22half2_rn(make_float2(acc[nt][0], acc[nt][1]));
        if (r1 < N_NODES)
            *reinterpret_cast<__half2*>(Yh + r1 * MOUT + c) =
                __float22half2_rn(make_float2(acc[nt][2], acc[nt][3]));
    }
}

// ---------------- GAT helpers ----------------
__device__ __forceinline__ float eluf(float x) {
    return x > 0.f ? x : expm1f(x);
}

__device__ __forceinline__ void cvt8(uint4 u, float2& a, float2& b, float2& c, float2& d) {
    a = __half22float2(*reinterpret_cast<__half2*>(&u.x));
    b = __half22float2(*reinterpret_cast<__half2*>(&u.y));
    c = __half22float2(*reinterpret_cast<__half2*>(&u.z));
    d = __half22float2(*reinterpret_cast<__half2*>(&u.w));
}

// ---------------- GAT layer 1: FULL warp/node, edges split across two 16-lane halves ----------------
__global__ __launch_bounds__(256) void k_gat1() {
    int t = blockIdx.x * blockDim.x + threadIdx.x;
    int w = t >> 5;                        // node per full warp
    if (w >= N_NODES) return;
    int lane16 = threadIdx.x & 15;         // dim-lane within half
    int grp = (threadIdx.x >> 4) & 1;      // which edge-half this lane processes
    unsigned hmask = 0xFFFFu << (threadIdx.x & 16);  // 16-lane group mask

    const __half* fp = g_feat1h;
    uint4 ud = *reinterpret_cast<const uint4*>(fp + w * 128 + lane16 * 8);
    float2 d0, d1, d2, d3;
    cvt8(ud, d0, d1, d2, d3);

    float c0 = 0.f, c1 = 0.f, c2 = 0.f, c3 = 0.f;
    float c4 = 0.f, c5 = 0.f, c6 = 0.f, c7 = 0.f;
    float den = 0.f;

    int beg = g_rs[w], endall = g_rs[w + 1];
    int half = (endall - beg + 1) >> 1;
    int i   = grp ? (beg + half) : beg;
    int end = grp ? endall : (beg + half);

    for (; i + 1 < end; i += 2) {
        int s0 = g_col[i], s1 = g_col[i + 1];
        uint4 u0 = *reinterpret_cast<const uint4*>(fp + s0 * 128 + lane16 * 8);
        uint4 u1 = *reinterpret_cast<const uint4*>(fp + s1 * 128 + lane16 * 8);
        float2 a0, a1, a2, a3, b0, b1, b2, b3;
        cvt8(u0, a0, a1, a2, a3);
        cvt8(u1, b0, b1, b2, b3);
        float p0 = a0.x * d0.x + a0.y * d0.y + a1.x * d1.x + a1.y * d1.y
                 + a2.x * d2.x + a2.y * d2.y + a3.x * d3.x + a3.y * d3.y;
        float p1 = b0.x * d0.x + b0.y * d0.y + b1.x * d1.x + b1.y * d1.y
                 + b2.x * d2.x + b2.y * d2.y + b3.x * d3.x + b3.y * d3.y;
        p0 += __shfl_xor_sync(hmask, p0, 1);
        p1 += __shfl_xor_sync(hmask, p1, 1);
        float q0 = __expf(p0 * 0.25f);     // HIDDEN^-0.5
        float q1 = __expf(p1 * 0.25f);
        den += q0 + q1;
        c0 += q0 * a0.x + q1 * b0.x;
        c1 += q0 * a0.y + q1 * b0.y;
        c2 += q0 * a1.x + q1 * b1.x;
        c3 += q0 * a1.y + q1 * b1.y;
        c4 += q0 * a2.x + q1 * b2.x;
        c5 += q0 * a2.y + q1 * b2.y;
        c6 += q0 * a3.x + q1 * b3.x;
        c7 += q0 * a3.y + q1 * b3.y;
    }
    if (i < end) {
        int s0 = g_col[i];
        uint4 u0 = *reinterpret_cast<const uint4*>(fp + s0 * 128 + lane16 * 8);
        float2 a0, a1, a2, a3;
        cvt8(u0, a0, a1, a2, a3);
        float p0 = a0.x * d0.x + a0.y * d0.y + a1.x * d1.x + a1.y * d1.y
                 + a2.x * d2.x + a2.y * d2.y + a3.x * d3.x + a3.y * d3.y;
        p0 += __shfl_xor_sync(hmask, p0, 1);
        float q0 = __expf(p0 * 0.25f);
        den += q0;
        c0 += q0 * a0.x; c1 += q0 * a0.y; c2 += q0 * a1.x; c3 += q0 * a1.y;
        c4 += q0 * a2.x; c5 += q0 * a2.y; c6 += q0 * a3.x; c7 += q0 * a3.y;
    }

    // combine halves (warp fully converged here)
    den += __shfl_xor_sync(0xffffffffu, den, 16);
    c0 += __shfl_xor_sync(0xffffffffu, c0, 16);
    c1 += __shfl_xor_sync(0xffffffffu, c1, 16);
    c2 += __shfl_xor_sync(0xffffffffu, c2, 16);
    c3 += __shfl_xor_sync(0xffffffffu, c3, 16);
    c4 += __shfl_xor_sync(0xffffffffu, c4, 16);
    c5 += __shfl_xor_sync(0xffffffffu, c5, 16);
    c6 += __shfl_xor_sync(0xffffffffu, c6, 16);
    c7 += __shfl_xor_sync(0xffffffffu, c7, 16);

    if (grp == 0) {
        float inv = 1.f / fmaxf(den, 1e-9f);
        float* op = g_h1 + w * 128 + lane16 * 8;
        *reinterpret_cast<float4*>(op) =
            make_float4(eluf(c0 * inv), eluf(c1 * inv), eluf(c2 * inv), eluf(c3 * inv));
        *reinterpret_cast<float4*>(op + 4) =
            make_float4(eluf(c4 * inv), eluf(c5 * inv), eluf(c6 * inv), eluf(c7 * inv));
    }
}

// ---------------- GAT layer 2: 16 lanes/node, edges split across two 8-lane groups ----------------
__global__ __launch_bounds__(256) void k_gat2(float* __restrict__ out) {
    int t = blockIdx.x * blockDim.x + threadIdx.x;
    int w = t >> 4;                        // node per 16-lane window
    if (w >= N_NODES) return;
    int lane8 = threadIdx.x & 7;           // dim-lane within 8-group
    int sub = (threadIdx.x >> 3) & 1;      // which edge-half
    unsigned gmask = 0xFFu << (threadIdx.x & 24);    // 8-lane group mask
    unsigned wmask = 0xFFFFu << (threadIdx.x & 16);  // 16-lane window mask

    const __half* fp = g_feat2h;
    uint4 ud = *reinterpret_cast<const uint4*>(fp + w * 64 + lane8 * 8);
    float2 d0, d1, d2, d3;
    cvt8(ud, d0, d1, d2, d3);

    float c0 = 0.f, c1 = 0.f, c2 = 0.f, c3 = 0.f;
    float c4 = 0.f, c5 = 0.f, c6 = 0.f, c7 = 0.f;
    float den = 0.f;

    int beg = g_rs[w], endall = g_rs[w + 1];
    int half = (endall - beg + 1) >> 1;
    int i   = sub ? (beg + half) : beg;
    int end = sub ? endall : (beg + half);

    for (; i + 1 < end; i += 2) {
        int s0 = g_col[i], s1 = g_col[i + 1];
        uint4 u0 = *reinterpret_cast<const uint4*>(fp + s0 * 64 + lane8 * 8);
        uint4 u1 = *reinterpret_cast<const uint4*>(fp + s1 * 64 + lane8 * 8);
        float2 a0, a1, a2, a3, b0, b1, b2, b3;
        cvt8(u0, a0, a1, a2, a3);
        cvt8(u1, b0, b1, b2, b3);
        float p0 = a0.x * d0.x + a0.y * d0.y + a1.x * d1.x + a1.y * d1.y
                 + a2.x * d2.x + a2.y * d2.y + a3.x * d3.x + a3.y * d3.y;
        float p1 = b0.x * d0.x + b0.y * d0.y + b1.x * d1.x + b1.y * d1.y
                 + b2.x * d2.x + b2.y * d2.y + b3.x * d3.x + b3.y * d3.y;
#pragma unroll
        for (int off = 4; off; off >>= 1) {
            p0 += __shfl_xor_sync(gmask, p0, off);
            p1 += __shfl_xor_sync(gmask, p1, off);
        }
        float q0 = __expf(p0 * 0.125f);    // 64^-0.5
        float q1 = __expf(p1 * 0.125f);
        den += q0 + q1;
        c0 += q0 * a0.x + q1 * b0.x;
        c1 += q0 * a0.y + q1 * b0.y;
        c2 += q0 * a1.x + q1 * b1.x;
        c3 += q0 * a1.y + q1 * b1.y;
        c4 += q0 * a2.x + q1 * b2.x;
        c5 += q0 * a2.y + q1 * b2.y;
        c6 += q0 * a3.x + q1 * b3.x;
        c7 += q0 * a3.y + q1 * b3.y;
    }
    if (i < end) {
        int s0 = g_col[i];
        uint4 u0 = *reinterpret_cast<const uint4*>(fp + s0 * 64 + lane8 * 8);
        float2 a0, a1, a2, a3;
        cvt8(u0, a0, a1, a2, a3);
        float p0 = a0.x * d0.x + a0.y * d0.y + a1.x * d1.x + a1.y * d1.y
                 + a2.x * d2.x + a2.y * d2.y + a3.x * d3.x + a3.y * d3.y;
#pragma unroll
        for (int off = 4; off; off >>= 1)
            p0 += __shfl_xor_sync(gmask, p0, off);
        float q0 = __expf(p0 * 0.125f);
        den += q0;
        c0 += q0 * a0.x; c1 += q0 * a0.y; c2 += q0 * a1.x; c3 += q0 * a1.y;
        c4 += q0 * a2.x; c5 += q0 * a2.y; c6 += q0 * a3.x; c7 += q0 * a3.y;
    }

    // combine the two 8-lane halves (16-lane window converged here)
    den += __shfl_xor_sync(wmask, den, 8);
    c0 += __shfl_xor_sync(wmask, c0, 8);
    c1 += __shfl_xor_sync(wmask, c1, 8);
    c2 += __shfl_xor_sync(wmask, c2, 8);
    c3 += __shfl_xor_sync(wmask, c3, 8);
    c4 += __shfl_xor_sync(wmask, c4, 8);
    c5 += __shfl_xor_sync(wmask, c5, 8);
    c6 += __shfl_xor_sync(wmask, c6, 8);
    c7 += __shfl_xor_sync(wmask, c7, 8);

    if (sub == 0) {
        float inv = 1.f / fmaxf(den, 1e-9f);
        float* op = out + w * 64 + lane8 * 8;
        *reinterpret_cast<float4*>(op) = make_float4(c0 * inv, c1 * inv, c2 * inv, c3 * inv);
        *reinterpret_cast<float4*>(op + 4) = make_float4(c4 * inv, c5 * inv, c6 * inv, c7 * inv);
    }
}

// ---------------- launch (R11 structure: plain side stream, fork first) ----------------
extern "C" void kernel_launch(void* const* d_in, const int* in_sizes, int n_in,
                              void* d_out, int out_size) {
    const float* h   = (const float*)d_in[0];
    const float* W1  = (const float*)d_in[1];
    const float* W2  = (const float*)d_in[2];
    const int*   src = (const int*)d_in[3];
    const int*   dst = (const int*)d_in[4];
    float*       out = (float*)d_out;

    __half *p_f1h = nullptr, *p_f2h = nullptr;
    float  *p_h1 = nullptr;
    int    *p_deg = nullptr;
    cudaGetSymbolAddress((void**)&p_f1h, g_feat1h);
    cudaGetSymbolAddress((void**)&p_h1, g_h1);
    cudaGetSymbolAddress((void**)&p_f2h, g_feat2h);
    cudaGetSymbolAddress((void**)&p_deg, g_deg);

    static cudaStream_t s_side = nullptr;
    static cudaEvent_t ev_fork = nullptr, ev_join = nullptr;
    if (s_side == nullptr) {
        cudaStreamCreateWithFlags(&s_side, cudaStreamNonBlocking);
        cudaEventCreateWithFlags(&ev_fork, cudaEventDisableTiming);
        cudaEventCreateWithFlags(&ev_join, cudaEventDisableTiming);
    }

    const int TB = 256;
    const int GB = (N_NODES + 127) / 128;  // 391
    const int EB = (N_EDGES / 4 + TB - 1) / TB;

    // fork: gemm1 on side stream (independent of CSR build)
    cudaEventRecord(ev_fork, 0);
    cudaStreamWaitEvent(s_side, ev_fork, 0);
    k_gemm_tc<128><<<GB, 256, 0, s_side>>>(h, W1, p_f1h);
    cudaEventRecord(ev_join, s_side);

    // main stream: CSR build
    cudaMemsetAsync(p_deg, 0, N_NODES * sizeof(int));
    k_hist<<<EB, TB>>>(dst);
    k_scan<<<1, 1024>>>();
    k_fill<<<EB, TB>>>(src, dst);

    // join, then the dependent chain
    cudaStreamWaitEvent(0, ev_join, 0);
    k_gat1<<<(N_NODES * 32 + TB - 1) / TB, TB>>>();
    k_gemm_tc<64><<<GB, 256>>>(p_h1, W2, p_f2h);
    k_gat2<<<(N_NODES * 16 + TB - 1) / TB, TB>>>(out);
}